// round 2
// baseline (speedup 1.0000x reference)
#include <cuda_runtime.h>
#include <cstdint>

#define NODES 50000
#define F 64

// ---------------- scratch (device globals; no allocations allowed) ----------
__device__ float4 g_agg4[NODES * (F / 4)];   // [NODES, 64] accumulator
__device__ float4 g_h4[NODES * (F / 4)];     // [NODES, 64] layer-1 output
__device__ float  g_deg[NODES];
__device__ int    g_is32;                    // 1 if edge indices are int32

// ---------------- dtype sniff -----------------------------------------------
// Reference declares int64 indices, but default JAX canonicalizes to int32.
// Interpret first 256 int64 slots: genuine int64 indices are all in [0, N);
// int32 data reinterpreted as int64 is astronomically unlikely to pass.
__global__ void sniff_kernel(const long long* __restrict__ p) {
    long long v = p[threadIdx.x];
    int bad = (v < 0 || v >= (long long)NODES) ? 1 : 0;
    bad = __syncthreads_or(bad);
    if (threadIdx.x == 0) g_is32 = bad;
}

// ---------------- zero accumulators -----------------------------------------
__global__ void zero_kernel() {
    int i = blockIdx.x * blockDim.x + threadIdx.x;
    if (i < NODES * (F / 4)) g_agg4[i] = make_float4(0.f, 0.f, 0.f, 0.f);
    if (i < NODES) g_deg[i] = 0.f;
}

// ---------------- edge scatter: agg[col] += src[row]; deg[col] += 1 ---------
// 16 lanes per edge, one float4 red per lane (red.global.add.v4.f32, sm_90+).
__global__ void scatter_kernel(const float* __restrict__ src,
                               const void* __restrict__ ei, int E) {
    long long tid = (long long)blockIdx.x * blockDim.x + threadIdx.x;
    int e = (int)(tid >> 4);
    int j = (int)(tid & 15);
    if (e >= E) return;

    int row, col;
    if (g_is32) {
        const int* p = (const int*)ei;
        row = __ldg(p + e);
        col = __ldg(p + E + e);
    } else {
        const long long* p = (const long long*)ei;
        row = (int)__ldg(p + e);
        col = (int)__ldg(p + E + e);
    }

    float4 v = __ldg((const float4*)(src + (size_t)row * F) + j);
    float* dst = (float*)g_agg4 + (size_t)col * F + j * 4;
    asm volatile("red.global.add.v4.f32 [%0], {%1,%2,%3,%4};"
                 :: "l"(dst), "f"(v.x), "f"(v.y), "f"(v.z), "f"(v.w)
                 : "memory");
    if (j == 0) {
        float* dp = g_deg + col;
        asm volatile("red.global.add.f32 [%0], %1;" :: "l"(dp), "f"(1.0f)
                     : "memory");
    }
}

// ---------------- fused dense: out = (agg/deg)@W + b + xin@R  (opt relu) ----
// Tile: 64 nodes x 64 outputs per block, 256 threads, 4x4 register blocking.
// K processed as two 64-chunks: chunk0 = scaled agg vs W, chunk1 = xin vs R.
template <bool RELU>
__global__ void __launch_bounds__(256) dense_kernel(
    const float* __restrict__ xin,
    const float* __restrict__ W, const float* __restrict__ bias,
    const float* __restrict__ R, float* __restrict__ out, int n_nodes) {
    __shared__ float As[F][68];   // A-tile, k-major (transposed), padded
    __shared__ float Ws[F][F];    // weight tile
    __shared__ float sb[F];
    __shared__ float sscale[F];

    const float* agg = (const float*)g_agg4;
    int tid = threadIdx.x;
    int n0 = blockIdx.x * 64;

    if (tid < F) {
        sb[tid] = bias[tid];
        int n = n0 + tid;
        float d = (n < n_nodes) ? g_deg[n] : 1.f;
        sscale[tid] = 1.f / fmaxf(d, 1.f);
    }

    float acc[4][4];
#pragma unroll
    for (int a = 0; a < 4; a++)
#pragma unroll
        for (int b = 0; b < 4; b++) acc[a][b] = 0.f;

    int j0 = (tid & 15) * 4;
    int i0 = (tid >> 4) * 4;

#pragma unroll
    for (int c = 0; c < 2; ++c) {
        const float* src = c ? xin : agg;
        const float* wsrc = c ? R : W;
        __syncthreads();   // sscale ready (c=0) / previous compute done (c=1)
        // stage A transposed + W, 4 float4 per thread each
#pragma unroll
        for (int t = 0; t < 4; ++t) {
            int q = tid + 256 * t;          // [0,1024)
            int i = q >> 4;                 // node within tile
            int kk = (q & 15) << 2;         // k offset
            int n = n0 + i;
            float4 v = make_float4(0.f, 0.f, 0.f, 0.f);
            if (n < n_nodes) v = *(const float4*)(src + (size_t)n * F + kk);
            if (c == 0) {
                float s = sscale[i];
                v.x *= s; v.y *= s; v.z *= s; v.w *= s;
            }
            As[kk + 0][i] = v.x;
            As[kk + 1][i] = v.y;
            As[kk + 2][i] = v.z;
            As[kk + 3][i] = v.w;
            *(float4*)((float*)Ws + q * 4) = *(const float4*)(wsrc + q * 4);
        }
        __syncthreads();
#pragma unroll
        for (int k = 0; k < F; ++k) {
            float4 a = *(const float4*)&As[k][i0];
            float4 w = *(const float4*)&Ws[k][j0];
            acc[0][0] += a.x * w.x; acc[0][1] += a.x * w.y;
            acc[0][2] += a.x * w.z; acc[0][3] += a.x * w.w;
            acc[1][0] += a.y * w.x; acc[1][1] += a.y * w.y;
            acc[1][2] += a.y * w.z; acc[1][3] += a.y * w.w;
            acc[2][0] += a.z * w.x; acc[2][1] += a.z * w.y;
            acc[2][2] += a.z * w.z; acc[2][3] += a.z * w.w;
            acc[3][0] += a.w * w.x; acc[3][1] += a.w * w.y;
            acc[3][2] += a.w * w.z; acc[3][3] += a.w * w.w;
        }
    }

#pragma unroll
    for (int ii = 0; ii < 4; ++ii) {
        int n = n0 + i0 + ii;
        if (n < n_nodes) {
            float4 o;
            o.x = acc[ii][0] + sb[j0 + 0];
            o.y = acc[ii][1] + sb[j0 + 1];
            o.z = acc[ii][2] + sb[j0 + 2];
            o.w = acc[ii][3] + sb[j0 + 3];
            if (RELU) {
                o.x = fmaxf(o.x, 0.f); o.y = fmaxf(o.y, 0.f);
                o.z = fmaxf(o.z, 0.f); o.w = fmaxf(o.w, 0.f);
            }
            *(float4*)(out + (size_t)n * F + j0) = o;
        }
    }
}

// ---------------- row-wise L2 normalize (in place) --------------------------
__global__ void normalize_kernel(float* __restrict__ out, int n_nodes) {
    int g = blockIdx.x * blockDim.x + threadIdx.x;
    int node = g >> 5;
    int lane = g & 31;
    if (node >= n_nodes) return;
    float2 v = *(float2*)(out + (size_t)node * F + lane * 2);
    float ss = v.x * v.x + v.y * v.y;
#pragma unroll
    for (int off = 16; off > 0; off >>= 1)
        ss += __shfl_xor_sync(0xFFFFFFFFu, ss, off);
    float inv = 1.f / fmaxf(sqrtf(ss), 1e-12f);
    v.x *= inv; v.y *= inv;
    *(float2*)(out + (size_t)node * F + lane * 2) = v;
}

// ---------------- launch -----------------------------------------------------
extern "C" void kernel_launch(void* const* d_in, const int* in_sizes, int n_in,
                              void* d_out, int out_size) {
    const float* x  = (const float*)d_in[0];
    const void*  e0 = d_in[1];
    const void*  e1 = d_in[2];
    const float* W1 = (const float*)d_in[3];
    const float* b1 = (const float*)d_in[4];
    const float* R1 = (const float*)d_in[5];
    const float* W2 = (const float*)d_in[6];
    const float* b2 = (const float*)d_in[7];
    const float* R2 = (const float*)d_in[8];
    float* out = (float*)d_out;

    // Resolve scratch symbol address once (host API; no allocation, no stream op)
    static float* h4 = nullptr;
    if (!h4) {
        void* p = nullptr;
        cudaGetSymbolAddress(&p, g_h4);
        h4 = (float*)p;
    }

    int E = in_sizes[1] / 2;
    int n_nodes = out_size / F;           // 50000

    sniff_kernel<<<1, 256>>>((const long long*)e0);

    int zeroN = NODES * (F / 4);
    int zb = (zeroN + 255) / 256;
    long long sthreads = (long long)E * 16;
    int sb_ = (int)((sthreads + 255) / 256);
    int db = (n_nodes + 63) / 64;
    int nb = (n_nodes * 32 + 255) / 256;

    // Layer 1
    zero_kernel<<<zb, 256>>>();
    scatter_kernel<<<sb_, 256>>>(x, e0, E);
    dense_kernel<true><<<db, 256>>>(x, W1, b1, R1, h4, n_nodes);

    // Layer 2
    zero_kernel<<<zb, 256>>>();
    scatter_kernel<<<sb_, 256>>>(h4, e1, E);
    dense_kernel<false><<<db, 256>>>(h4, W2, b2, R2, out, n_nodes);

    normalize_kernel<<<nb, 256>>>(out, n_nodes);
}

// round 3
// speedup vs baseline: 1.2531x; 1.2531x over previous
#include <cuda_runtime.h>
#include <cstdint>

#define NODES 50000
#define F 64
#define E_MAX 2000000
#define SBS 512
#define SNB ((NODES + SBS - 1) / SBS)   // 98

// ---------------- scratch (device globals; no allocations allowed) ----------
__device__ float4 g_agg4[NODES * (F / 4)];   // [NODES, 64] mean-aggregated feats
__device__ float4 g_h4[NODES * (F / 4)];     // [NODES, 64] layer-1 output
__device__ int    g_cnt[NODES];              // per-dest edge counts
__device__ int    g_incl[NODES];             // per-block inclusive scan
__device__ int    g_bsum[SNB];               // block sums -> exclusive offsets
__device__ int    g_rowptr[NODES + 1];       // CSR row pointers (by dest)
__device__ int    g_cursor[NODES];           // placement cursors
__device__ int    g_csr[E_MAX];              // CSR source indices
__device__ int    g_is32;                    // 1 if edge indices are int32

// ---------------- dtype sniff -----------------------------------------------
// Reference declares int64 indices, but default JAX canonicalizes to int32.
__global__ void sniff_kernel(const long long* __restrict__ p) {
    long long v = p[threadIdx.x];
    int bad = (v < 0 || v >= (long long)NODES) ? 1 : 0;
    bad = __syncthreads_or(bad);
    if (threadIdx.x == 0) g_is32 = bad;
}

// ---------------- CSR build --------------------------------------------------
__global__ void zero_cnt_kernel() {
    int i = blockIdx.x * blockDim.x + threadIdx.x;
    if (i < NODES) g_cnt[i] = 0;
}

__global__ void count_kernel(const void* __restrict__ ei, int E) {
    int e = blockIdx.x * blockDim.x + threadIdx.x;
    if (e >= E) return;
    int col;
    if (g_is32) col = __ldg((const int*)ei + E + e);
    else        col = (int)__ldg((const long long*)ei + E + e);
    atomicAdd(&g_cnt[col], 1);
}

// per-block inclusive scan of g_cnt -> g_incl, block totals -> g_bsum
__global__ void __launch_bounds__(SBS) scan1_kernel() {
    int tid = threadIdx.x;
    int i = blockIdx.x * SBS + tid;
    int v = (i < NODES) ? g_cnt[i] : 0;
    int lane = tid & 31, warp = tid >> 5;
    int x = v;
#pragma unroll
    for (int o = 1; o < 32; o <<= 1) {
        int y = __shfl_up_sync(0xFFFFFFFFu, x, o);
        if (lane >= o) x += y;
    }
    __shared__ int ws[SBS / 32];
    if (lane == 31) ws[warp] = x;
    __syncthreads();
    if (warp == 0) {
        int s = (lane < SBS / 32) ? ws[lane] : 0;
#pragma unroll
        for (int o = 1; o < 32; o <<= 1) {
            int y = __shfl_up_sync(0xFFFFFFFFu, s, o);
            if (lane >= o) s += y;
        }
        if (lane < SBS / 32) ws[lane] = s;
    }
    __syncthreads();
    if (warp > 0) x += ws[warp - 1];
    if (i < NODES) g_incl[i] = x;
    if (tid == SBS - 1) g_bsum[blockIdx.x] = x;
}

// exclusive scan of block sums (single block)
__global__ void scan2_kernel() {
    int tid = threadIdx.x;             // 128 threads >= SNB
    int v = (tid < SNB) ? g_bsum[tid] : 0;
    int lane = tid & 31, warp = tid >> 5;
    int x = v;
#pragma unroll
    for (int o = 1; o < 32; o <<= 1) {
        int y = __shfl_up_sync(0xFFFFFFFFu, x, o);
        if (lane >= o) x += y;
    }
    __shared__ int ws[4];
    if (lane == 31) ws[warp] = x;
    __syncthreads();
    int off = 0;
    for (int w = 0; w < warp; w++) off += ws[w];
    x += off;
    if (tid < SNB) g_bsum[tid] = x - v;   // exclusive
}

__global__ void scan3_kernel() {
    int i = blockIdx.x * blockDim.x + threadIdx.x;
    if (i >= NODES) return;
    int val = g_incl[i] + g_bsum[i / SBS];
    g_rowptr[i + 1] = val;
    g_cursor[i] = val - g_cnt[i];
    if (i == 0) g_rowptr[0] = 0;
}

__global__ void place_kernel(const void* __restrict__ ei, int E) {
    int e = blockIdx.x * blockDim.x + threadIdx.x;
    if (e >= E) return;
    int row, col;
    if (g_is32) {
        const int* p = (const int*)ei;
        row = __ldg(p + e); col = __ldg(p + E + e);
    } else {
        const long long* p = (const long long*)ei;
        row = (int)__ldg(p + e); col = (int)__ldg(p + E + e);
    }
    int pos = atomicAdd(&g_cursor[col], 1);
    g_csr[pos] = row;
}

// ---------------- gather-side mean aggregation: one warp per node -----------
__global__ void __launch_bounds__(256) gather_kernel(
    const float* __restrict__ src) {
    int tid = threadIdx.x;
    int node = blockIdx.x * 8 + (tid >> 5);
    if (node >= NODES) return;
    int lane = tid & 31;
    int s = __ldg(&g_rowptr[node]);
    int e = __ldg(&g_rowptr[node + 1]);
    float ax = 0.f, ay = 0.f;
    int i = s;
    for (; i + 4 <= e; i += 4) {
        int r0 = __ldg(&g_csr[i + 0]);
        int r1 = __ldg(&g_csr[i + 1]);
        int r2 = __ldg(&g_csr[i + 2]);
        int r3 = __ldg(&g_csr[i + 3]);
        float2 v0 = *(const float2*)(src + (size_t)r0 * F + lane * 2);
        float2 v1 = *(const float2*)(src + (size_t)r1 * F + lane * 2);
        float2 v2 = *(const float2*)(src + (size_t)r2 * F + lane * 2);
        float2 v3 = *(const float2*)(src + (size_t)r3 * F + lane * 2);
        ax += v0.x + v1.x + v2.x + v3.x;
        ay += v0.y + v1.y + v2.y + v3.y;
    }
    for (; i < e; i++) {
        int r = __ldg(&g_csr[i]);
        float2 v = *(const float2*)(src + (size_t)r * F + lane * 2);
        ax += v.x; ay += v.y;
    }
    float inv = 1.f / (float)max(e - s, 1);
    float2 o; o.x = ax * inv; o.y = ay * inv;
    *(float2*)((float*)g_agg4 + (size_t)node * F + lane * 2) = o;
}

// ---------------- fused dense: out = agg@W + b + xin@R  (relu / l2norm) -----
// Tile: 128 nodes x 64 outputs, 256 threads, 8x4 register blocking.
// Dynamic smem: As[64][132] (k-major A), Ws[64][64], sb[64].
template <bool RELU, bool NORM>
__global__ void __launch_bounds__(256) dense_kernel(
    const float* __restrict__ xin,
    const float* __restrict__ W, const float* __restrict__ bias,
    const float* __restrict__ R, float* __restrict__ out, int n_nodes) {
    extern __shared__ float smem[];
    float* As = smem;                    // [64][132]
    float* Ws = smem + F * 132;          // [64][64]
    float* sb = Ws + F * F;              // [64]

    const float* agg = (const float*)g_agg4;
    int tid = threadIdx.x;
    int n0 = blockIdx.x * 128;

    if (tid < F) sb[tid] = bias[tid];

    float acc[8][4];
#pragma unroll
    for (int a = 0; a < 8; a++)
#pragma unroll
        for (int b = 0; b < 4; b++) acc[a][b] = 0.f;

    int j0 = (tid & 15) * 4;
    int i0 = (tid >> 4) * 8;

#pragma unroll
    for (int c = 0; c < 2; ++c) {
        const float* src = c ? xin : agg;
        const float* wsrc = c ? R : W;
        __syncthreads();
        // stage A transposed: 2048 float4 loads -> As[k][i]
#pragma unroll
        for (int t = 0; t < 8; ++t) {
            int q = tid + 256 * t;          // [0,2048)
            int i = q >> 4;                 // node within tile (0..127)
            int kk = (q & 15) << 2;         // k offset
            int n = n0 + i;
            float4 v = make_float4(0.f, 0.f, 0.f, 0.f);
            if (n < n_nodes) v = *(const float4*)(src + (size_t)n * F + kk);
            As[(kk + 0) * 132 + i] = v.x;
            As[(kk + 1) * 132 + i] = v.y;
            As[(kk + 2) * 132 + i] = v.z;
            As[(kk + 3) * 132 + i] = v.w;
        }
#pragma unroll
        for (int t = 0; t < 4; ++t) {
            int q = tid + 256 * t;          // [0,1024)
            *(float4*)(Ws + q * 4) = *(const float4*)(wsrc + q * 4);
        }
        __syncthreads();
#pragma unroll
        for (int k = 0; k < F; ++k) {
            float4 a0 = *(const float4*)&As[k * 132 + i0];
            float4 a1 = *(const float4*)&As[k * 132 + i0 + 4];
            float4 w = *(const float4*)&Ws[k * F + j0];
            acc[0][0] += a0.x * w.x; acc[0][1] += a0.x * w.y;
            acc[0][2] += a0.x * w.z; acc[0][3] += a0.x * w.w;
            acc[1][0] += a0.y * w.x; acc[1][1] += a0.y * w.y;
            acc[1][2] += a0.y * w.z; acc[1][3] += a0.y * w.w;
            acc[2][0] += a0.z * w.x; acc[2][1] += a0.z * w.y;
            acc[2][2] += a0.z * w.z; acc[2][3] += a0.z * w.w;
            acc[3][0] += a0.w * w.x; acc[3][1] += a0.w * w.y;
            acc[3][2] += a0.w * w.z; acc[3][3] += a0.w * w.w;
            acc[4][0] += a1.x * w.x; acc[4][1] += a1.x * w.y;
            acc[4][2] += a1.x * w.z; acc[4][3] += a1.x * w.w;
            acc[5][0] += a1.y * w.x; acc[5][1] += a1.y * w.y;
            acc[5][2] += a1.y * w.z; acc[5][3] += a1.y * w.w;
            acc[6][0] += a1.z * w.x; acc[6][1] += a1.z * w.y;
            acc[6][2] += a1.z * w.z; acc[6][3] += a1.z * w.w;
            acc[7][0] += a1.w * w.x; acc[7][1] += a1.w * w.y;
            acc[7][2] += a1.w * w.z; acc[7][3] += a1.w * w.w;
        }
    }

    // epilogue: bias (+relu) or bias + row L2-normalize
    float o[8][4];
#pragma unroll
    for (int ii = 0; ii < 8; ++ii) {
#pragma unroll
        for (int jj = 0; jj < 4; ++jj) {
            float v = acc[ii][jj] + sb[j0 + jj];
            if (RELU) v = fmaxf(v, 0.f);
            o[ii][jj] = v;
        }
    }
    if (NORM) {
        // each row's 64 cols live in 16 consecutive lanes (same tid>>4 group,
        // within one half-warp) -> shfl_xor over masks 1,2,4,8
#pragma unroll
        for (int ii = 0; ii < 8; ++ii) {
            float ss = o[ii][0] * o[ii][0] + o[ii][1] * o[ii][1] +
                       o[ii][2] * o[ii][2] + o[ii][3] * o[ii][3];
#pragma unroll
            for (int m = 1; m < 16; m <<= 1)
                ss += __shfl_xor_sync(0xFFFFFFFFu, ss, m);
            float inv = 1.f / fmaxf(sqrtf(ss), 1e-12f);
            o[ii][0] *= inv; o[ii][1] *= inv;
            o[ii][2] *= inv; o[ii][3] *= inv;
        }
    }
#pragma unroll
    for (int ii = 0; ii < 8; ++ii) {
        int n = n0 + i0 + ii;
        if (n < n_nodes) {
            float4 v = make_float4(o[ii][0], o[ii][1], o[ii][2], o[ii][3]);
            *(float4*)(out + (size_t)n * F + j0) = v;
        }
    }
}

// ---------------- launch -----------------------------------------------------
extern "C" void kernel_launch(void* const* d_in, const int* in_sizes, int n_in,
                              void* d_out, int out_size) {
    const float* x  = (const float*)d_in[0];
    const void*  e0 = d_in[1];
    const void*  e1 = d_in[2];
    const float* W1 = (const float*)d_in[3];
    const float* b1 = (const float*)d_in[4];
    const float* R1 = (const float*)d_in[5];
    const float* W2 = (const float*)d_in[6];
    const float* b2 = (const float*)d_in[7];
    const float* R2 = (const float*)d_in[8];
    float* out = (float*)d_out;

    static float* h4 = nullptr;
    if (!h4) {
        void* p = nullptr;
        cudaGetSymbolAddress(&p, g_h4);
        h4 = (float*)p;
        // opt-in to >48KB dynamic smem for the dense kernels
        cudaFuncSetAttribute(dense_kernel<true, false>,
                             cudaFuncAttributeMaxDynamicSharedMemorySize, 51200);
        cudaFuncSetAttribute(dense_kernel<false, true>,
                             cudaFuncAttributeMaxDynamicSharedMemorySize, 51200);
    }

    int E = in_sizes[1] / 2;
    int n_nodes = out_size / F;           // 50000
    int dsmem = (F * 132 + F * F + F) * 4;  // 50432 B

    int eb = (E + 255) / 256;
    int nb = (NODES + 255) / 256;
    int gb = (NODES + 7) / 8;
    int db = (n_nodes + 127) / 128;

    sniff_kernel<<<1, 256>>>((const long long*)e0);

    // ---- layer 1 ----
    zero_cnt_kernel<<<nb, 256>>>();
    count_kernel<<<eb, 256>>>(e0, E);
    scan1_kernel<<<SNB, SBS>>>();
    scan2_kernel<<<1, 128>>>();
    scan3_kernel<<<nb, 256>>>();
    place_kernel<<<eb, 256>>>(e0, E);
    gather_kernel<<<gb, 256>>>(x);
    dense_kernel<true, false><<<db, 256, dsmem>>>(x, W1, b1, R1, h4, n_nodes);

    // ---- layer 2 ----
    zero_cnt_kernel<<<nb, 256>>>();
    count_kernel<<<eb, 256>>>(e1, E);
    scan1_kernel<<<SNB, SBS>>>();
    scan2_kernel<<<1, 128>>>();
    scan3_kernel<<<nb, 256>>>();
    place_kernel<<<eb, 256>>>(e1, E);
    gather_kernel<<<gb, 256>>>(h4);
    dense_kernel<false, true><<<db, 256, dsmem>>>(h4, W2, b2, R2, out, n_nodes);
}

// round 4
// speedup vs baseline: 1.3409x; 1.0700x over previous
#include <cuda_runtime.h>
#include <cuda_fp16.h>
#include <cstdint>

#define NODES 50000
#define F 64
#define E_MAX 2000000
#define SBS 512
#define SNB ((NODES + SBS - 1) / SBS)   // 98

// ---------------- scratch (device globals; no allocations allowed) ----------
__device__ float4 g_agg4[NODES * (F / 4)];   // [NODES,64] mean-aggregated feats
__device__ float4 g_h4[NODES * (F / 4)];     // [NODES,64] layer-1 output (fp32)
__device__ __half g_xh[NODES * F];           // fp16 copy of x   (gather feed)
__device__ __half g_hh[NODES * F];           // fp16 copy of h   (gather feed)
__device__ int    g_is32;                    // 1 if edge indices are int32

// CSR set 0 (layer 1) and set 1 (layer 2, built concurrently on stream B)
__device__ int g_cnt0[NODES],  g_incl0[NODES], g_bsum0[SNB];
__device__ int g_rowptr0[NODES + 1], g_cursor0[NODES], g_csr0[E_MAX];
__device__ int g_cnt1[NODES],  g_incl1[NODES], g_bsum1[SNB];
__device__ int g_rowptr1[NODES + 1], g_cursor1[NODES], g_csr1[E_MAX];

// ---------------- f32x2 packed-FMA helpers (FFMA2, sm_100+) ------------------
__device__ __forceinline__ unsigned long long pk2(float a) {
    unsigned long long r;
    asm("mov.b64 %0, {%1, %1};" : "=l"(r) : "f"(a));
    return r;
}
__device__ __forceinline__ void fma2(unsigned long long& d,
                                     unsigned long long a,
                                     unsigned long long b) {
    asm("fma.rn.f32x2 %0, %1, %2, %0;" : "+l"(d) : "l"(a), "l"(b));
}
__device__ __forceinline__ float2 up2(unsigned long long v) {
    float2 f;
    asm("mov.b64 {%0, %1}, %2;" : "=f"(f.x), "=f"(f.y) : "l"(v));
    return f;
}

// ---------------- dtype sniff -----------------------------------------------
// Reference declares int64 indices, but default JAX canonicalizes to int32.
__global__ void sniff_kernel(const long long* __restrict__ p) {
    long long v = p[threadIdx.x];
    int bad = (v < 0 || v >= (long long)NODES) ? 1 : 0;
    bad = __syncthreads_or(bad);
    if (threadIdx.x == 0) g_is32 = bad;
}

// ---------------- fp32 -> fp16 conversion -----------------------------------
__global__ void tohalf_kernel(const float* __restrict__ src,
                              __half* __restrict__ dst, int n4) {
    int i = blockIdx.x * blockDim.x + threadIdx.x;
    if (i >= n4) return;
    float4 v = ((const float4*)src)[i];
    union { __half2 h[2]; uint2 u; } cv;
    cv.h[0] = __floats2half2_rn(v.x, v.y);
    cv.h[1] = __floats2half2_rn(v.z, v.w);
    ((uint2*)dst)[i] = cv.u;
}

// ---------------- CSR build (parameterized over scratch set) ----------------
__global__ void zero_cnt_kernel(int* __restrict__ cnt) {
    int i = blockIdx.x * blockDim.x + threadIdx.x;
    if (i < NODES) cnt[i] = 0;
}

__global__ void count_kernel(const void* __restrict__ ei, int E,
                             int* __restrict__ cnt) {
    int e = blockIdx.x * blockDim.x + threadIdx.x;
    if (e >= E) return;
    int col;
    if (g_is32) col = __ldg((const int*)ei + E + e);
    else        col = (int)__ldg((const long long*)ei + E + e);
    atomicAdd(&cnt[col], 1);
}

__global__ void __launch_bounds__(SBS) scan1_kernel(
    const int* __restrict__ cnt, int* __restrict__ incl,
    int* __restrict__ bsum) {
    int tid = threadIdx.x;
    int i = blockIdx.x * SBS + tid;
    int v = (i < NODES) ? cnt[i] : 0;
    int lane = tid & 31, warp = tid >> 5;
    int x = v;
#pragma unroll
    for (int o = 1; o < 32; o <<= 1) {
        int y = __shfl_up_sync(0xFFFFFFFFu, x, o);
        if (lane >= o) x += y;
    }
    __shared__ int ws[SBS / 32];
    if (lane == 31) ws[warp] = x;
    __syncthreads();
    if (warp == 0) {
        int s = (lane < SBS / 32) ? ws[lane] : 0;
#pragma unroll
        for (int o = 1; o < 32; o <<= 1) {
            int y = __shfl_up_sync(0xFFFFFFFFu, s, o);
            if (lane >= o) s += y;
        }
        if (lane < SBS / 32) ws[lane] = s;
    }
    __syncthreads();
    if (warp > 0) x += ws[warp - 1];
    if (i < NODES) incl[i] = x;
    if (tid == SBS - 1) bsum[blockIdx.x] = x;
}

__global__ void scan2_kernel(int* __restrict__ bsum) {
    int tid = threadIdx.x;             // 128 threads >= SNB
    int v = (tid < SNB) ? bsum[tid] : 0;
    int lane = tid & 31, warp = tid >> 5;
    int x = v;
#pragma unroll
    for (int o = 1; o < 32; o <<= 1) {
        int y = __shfl_up_sync(0xFFFFFFFFu, x, o);
        if (lane >= o) x += y;
    }
    __shared__ int ws[4];
    if (lane == 31) ws[warp] = x;
    __syncthreads();
    int off = 0;
    for (int w = 0; w < warp; w++) off += ws[w];
    x += off;
    if (tid < SNB) bsum[tid] = x - v;   // exclusive
}

__global__ void scan3_kernel(const int* __restrict__ cnt,
                             const int* __restrict__ incl,
                             const int* __restrict__ bsum,
                             int* __restrict__ rowptr,
                             int* __restrict__ cursor) {
    int i = blockIdx.x * blockDim.x + threadIdx.x;
    if (i >= NODES) return;
    int val = incl[i] + bsum[i / SBS];
    rowptr[i + 1] = val;
    cursor[i] = val - cnt[i];
    if (i == 0) rowptr[0] = 0;
}

__global__ void place_kernel(const void* __restrict__ ei, int E,
                             int* __restrict__ cursor,
                             int* __restrict__ csr) {
    int e = blockIdx.x * blockDim.x + threadIdx.x;
    if (e >= E) return;
    int row, col;
    if (g_is32) {
        const int* p = (const int*)ei;
        row = __ldg(p + e); col = __ldg(p + E + e);
    } else {
        const long long* p = (const long long*)ei;
        row = (int)__ldg(p + e); col = (int)__ldg(p + E + e);
    }
    int pos = atomicAdd(&cursor[col], 1);
    csr[pos] = row;
}

// ---------------- gather-side mean aggregation (fp16 feed, fp32 acc) --------
// one warp per node; each lane owns 2 columns (half2)
__global__ void __launch_bounds__(256) gather_kernel(
    const __half* __restrict__ srch,
    const int* __restrict__ rowptr, const int* __restrict__ csr) {
    int tid = threadIdx.x;
    int node = blockIdx.x * 8 + (tid >> 5);
    if (node >= NODES) return;
    int lane = tid & 31;
    int s = __ldg(&rowptr[node]);
    int e = __ldg(&rowptr[node + 1]);
    float ax = 0.f, ay = 0.f;
    int i = s;
    for (; i + 4 <= e; i += 4) {
        int r0 = __ldg(&csr[i + 0]);
        int r1 = __ldg(&csr[i + 1]);
        int r2 = __ldg(&csr[i + 2]);
        int r3 = __ldg(&csr[i + 3]);
        float2 v0 = __half22float2(*((const __half2*)(srch + (size_t)r0 * F) + lane));
        float2 v1 = __half22float2(*((const __half2*)(srch + (size_t)r1 * F) + lane));
        float2 v2 = __half22float2(*((const __half2*)(srch + (size_t)r2 * F) + lane));
        float2 v3 = __half22float2(*((const __half2*)(srch + (size_t)r3 * F) + lane));
        ax += v0.x + v1.x + v2.x + v3.x;
        ay += v0.y + v1.y + v2.y + v3.y;
    }
    for (; i < e; i++) {
        int r = __ldg(&csr[i]);
        float2 v = __half22float2(*((const __half2*)(srch + (size_t)r * F) + lane));
        ax += v.x; ay += v.y;
    }
    float inv = 1.f / (float)max(e - s, 1);
    float2 o; o.x = ax * inv; o.y = ay * inv;
    *(float2*)((float*)g_agg4 + (size_t)node * F + lane * 2) = o;
}

// ---------------- fused dense: out = agg@W + b + xin@R ----------------------
// 128 nodes x 64 outputs, 256 threads, 8x4 blocking via packed FFMA2.
// RELU path additionally emits fp16 copy of the output into g_hh.
template <bool RELU, bool NORM>
__global__ void __launch_bounds__(256) dense_kernel(
    const float* __restrict__ xin,
    const float* __restrict__ W, const float* __restrict__ bias,
    const float* __restrict__ R, float* __restrict__ out, int n_nodes) {
    extern __shared__ float smem[];
    float* As = smem;                    // [64][132]
    float* Ws = smem + F * 132;          // [64][64]
    float* sb = Ws + F * F;              // [64]

    const float* agg = (const float*)g_agg4;
    int tid = threadIdx.x;
    int n0 = blockIdx.x * 128;

    if (tid < F) sb[tid] = bias[tid];

    unsigned long long acc2[8][2];
#pragma unroll
    for (int a = 0; a < 8; a++) { acc2[a][0] = 0ull; acc2[a][1] = 0ull; }

    int j0 = (tid & 15) * 4;
    int i0 = (tid >> 4) * 8;

#pragma unroll
    for (int c = 0; c < 2; ++c) {
        const float* src = c ? xin : agg;
        const float* wsrc = c ? R : W;
        __syncthreads();
#pragma unroll
        for (int t = 0; t < 8; ++t) {
            int q = tid + 256 * t;          // [0,2048)
            int i = q >> 4;                 // node within tile (0..127)
            int kk = (q & 15) << 2;         // k offset
            int n = n0 + i;
            float4 v = make_float4(0.f, 0.f, 0.f, 0.f);
            if (n < n_nodes) v = *(const float4*)(src + (size_t)n * F + kk);
            As[(kk + 0) * 132 + i] = v.x;
            As[(kk + 1) * 132 + i] = v.y;
            As[(kk + 2) * 132 + i] = v.z;
            As[(kk + 3) * 132 + i] = v.w;
        }
#pragma unroll
        for (int t = 0; t < 4; ++t) {
            int q = tid + 256 * t;          // [0,1024)
            *(float4*)(Ws + q * 4) = *(const float4*)(wsrc + q * 4);
        }
        __syncthreads();
#pragma unroll
        for (int k = 0; k < F; ++k) {
            float4 a0 = *(const float4*)&As[k * 132 + i0];
            float4 a1 = *(const float4*)&As[k * 132 + i0 + 4];
            ulonglong2 wv = *(const ulonglong2*)&Ws[k * F + j0];
            unsigned long long p;
            p = pk2(a0.x); fma2(acc2[0][0], p, wv.x); fma2(acc2[0][1], p, wv.y);
            p = pk2(a0.y); fma2(acc2[1][0], p, wv.x); fma2(acc2[1][1], p, wv.y);
            p = pk2(a0.z); fma2(acc2[2][0], p, wv.x); fma2(acc2[2][1], p, wv.y);
            p = pk2(a0.w); fma2(acc2[3][0], p, wv.x); fma2(acc2[3][1], p, wv.y);
            p = pk2(a1.x); fma2(acc2[4][0], p, wv.x); fma2(acc2[4][1], p, wv.y);
            p = pk2(a1.y); fma2(acc2[5][0], p, wv.x); fma2(acc2[5][1], p, wv.y);
            p = pk2(a1.z); fma2(acc2[6][0], p, wv.x); fma2(acc2[6][1], p, wv.y);
            p = pk2(a1.w); fma2(acc2[7][0], p, wv.x); fma2(acc2[7][1], p, wv.y);
        }
    }

    // epilogue
    float o[8][4];
#pragma unroll
    for (int ii = 0; ii < 8; ++ii) {
        float2 lo = up2(acc2[ii][0]);
        float2 hi = up2(acc2[ii][1]);
        o[ii][0] = lo.x + sb[j0 + 0];
        o[ii][1] = lo.y + sb[j0 + 1];
        o[ii][2] = hi.x + sb[j0 + 2];
        o[ii][3] = hi.y + sb[j0 + 3];
        if (RELU) {
            o[ii][0] = fmaxf(o[ii][0], 0.f); o[ii][1] = fmaxf(o[ii][1], 0.f);
            o[ii][2] = fmaxf(o[ii][2], 0.f); o[ii][3] = fmaxf(o[ii][3], 0.f);
        }
    }
    if (NORM) {
        // each row's 64 cols live in 16 lanes of one half-warp -> xor 1,2,4,8
#pragma unroll
        for (int ii = 0; ii < 8; ++ii) {
            float ss = o[ii][0] * o[ii][0] + o[ii][1] * o[ii][1] +
                       o[ii][2] * o[ii][2] + o[ii][3] * o[ii][3];
#pragma unroll
            for (int m = 1; m < 16; m <<= 1)
                ss += __shfl_xor_sync(0xFFFFFFFFu, ss, m);
            float inv = 1.f / fmaxf(sqrtf(ss), 1e-12f);
            o[ii][0] *= inv; o[ii][1] *= inv;
            o[ii][2] *= inv; o[ii][3] *= inv;
        }
    }
#pragma unroll
    for (int ii = 0; ii < 8; ++ii) {
        int n = n0 + i0 + ii;
        if (n < n_nodes) {
            float4 v = make_float4(o[ii][0], o[ii][1], o[ii][2], o[ii][3]);
            *(float4*)(out + (size_t)n * F + j0) = v;
            if (RELU) {   // fp16 copy for the next gather
                union { __half2 h[2]; uint2 u; } cv;
                cv.h[0] = __floats2half2_rn(o[ii][0], o[ii][1]);
                cv.h[1] = __floats2half2_rn(o[ii][2], o[ii][3]);
                *(uint2*)(g_hh + (size_t)n * F + j0) = cv.u;
            }
        }
    }
}

// ---------------- host-side symbol/stream cache ------------------------------
struct Ctx {
    float* h4; __half* xh; __half* hh;
    int *cnt0, *incl0, *bsum0, *rowptr0, *cursor0, *csr0;
    int *cnt1, *incl1, *bsum1, *rowptr1, *cursor1, *csr1;
    cudaStream_t s2;
    cudaEvent_t evA, evXH, evCSR;
};
static Ctx* ctx() {
    static Ctx c;
    static bool init = false;
    if (!init) {
        void* p;
#define SYM(dst, s) cudaGetSymbolAddress(&p, s); c.dst = (decltype(c.dst))p
        SYM(h4, g_h4); SYM(xh, g_xh); SYM(hh, g_hh);
        SYM(cnt0, g_cnt0); SYM(incl0, g_incl0); SYM(bsum0, g_bsum0);
        SYM(rowptr0, g_rowptr0); SYM(cursor0, g_cursor0); SYM(csr0, g_csr0);
        SYM(cnt1, g_cnt1); SYM(incl1, g_incl1); SYM(bsum1, g_bsum1);
        SYM(rowptr1, g_rowptr1); SYM(cursor1, g_cursor1); SYM(csr1, g_csr1);
#undef SYM
        cudaStreamCreateWithFlags(&c.s2, cudaStreamNonBlocking);
        cudaEventCreateWithFlags(&c.evA, cudaEventDisableTiming);
        cudaEventCreateWithFlags(&c.evXH, cudaEventDisableTiming);
        cudaEventCreateWithFlags(&c.evCSR, cudaEventDisableTiming);
        cudaFuncSetAttribute(dense_kernel<true, false>,
                             cudaFuncAttributeMaxDynamicSharedMemorySize, 51200);
        cudaFuncSetAttribute(dense_kernel<false, true>,
                             cudaFuncAttributeMaxDynamicSharedMemorySize, 51200);
        init = true;
    }
    return &c;
}

// ---------------- launch -----------------------------------------------------
extern "C" void kernel_launch(void* const* d_in, const int* in_sizes, int n_in,
                              void* d_out, int out_size) {
    const float* x  = (const float*)d_in[0];
    const void*  e0 = d_in[1];
    const void*  e1 = d_in[2];
    const float* W1 = (const float*)d_in[3];
    const float* b1 = (const float*)d_in[4];
    const float* R1 = (const float*)d_in[5];
    const float* W2 = (const float*)d_in[6];
    const float* b2 = (const float*)d_in[7];
    const float* R2 = (const float*)d_in[8];
    float* out = (float*)d_out;

    Ctx* c = ctx();
    int E = in_sizes[1] / 2;
    int n_nodes = out_size / F;              // 50000
    int dsmem = (F * 132 + F * F + F) * 4;   // 50432 B

    int eb = (E + 255) / 256;
    int nb = (NODES + 255) / 256;
    int gb = (NODES + 7) / 8;
    int db = (n_nodes + 127) / 128;
    int cb = (NODES * F / 4 + 255) / 256;

    // ---- fork point: sniff gates both streams ----
    sniff_kernel<<<1, 256>>>((const long long*)e0);
    cudaEventRecord(c->evA, 0);
    cudaStreamWaitEvent(c->s2, c->evA, 0);

    // ---- stream B: x->fp16, then CSR build for layer 2 ----
    tohalf_kernel<<<cb, 256, 0, c->s2>>>(x, c->xh, NODES * F / 4);
    cudaEventRecord(c->evXH, c->s2);
    zero_cnt_kernel<<<nb, 256, 0, c->s2>>>(c->cnt1);
    count_kernel<<<eb, 256, 0, c->s2>>>(e1, E, c->cnt1);
    scan1_kernel<<<SNB, SBS, 0, c->s2>>>(c->cnt1, c->incl1, c->bsum1);
    scan2_kernel<<<1, 128, 0, c->s2>>>(c->bsum1);
    scan3_kernel<<<nb, 256, 0, c->s2>>>(c->cnt1, c->incl1, c->bsum1,
                                        c->rowptr1, c->cursor1);
    place_kernel<<<eb, 256, 0, c->s2>>>(e1, E, c->cursor1, c->csr1);
    cudaEventRecord(c->evCSR, c->s2);

    // ---- main stream: CSR build for layer 1 ----
    zero_cnt_kernel<<<nb, 256>>>(c->cnt0);
    count_kernel<<<eb, 256>>>(e0, E, c->cnt0);
    scan1_kernel<<<SNB, SBS>>>(c->cnt0, c->incl0, c->bsum0);
    scan2_kernel<<<1, 128>>>(c->bsum0);
    scan3_kernel<<<nb, 256>>>(c->cnt0, c->incl0, c->bsum0,
                              c->rowptr0, c->cursor0);
    place_kernel<<<eb, 256>>>(e0, E, c->cursor0, c->csr0);

    // ---- layer 1 ----
    cudaStreamWaitEvent(0, c->evXH, 0);
    gather_kernel<<<gb, 256>>>(c->xh, c->rowptr0, c->csr0);
    dense_kernel<true, false><<<db, 256, dsmem>>>(x, W1, b1, R1, c->h4,
                                                  n_nodes);

    // ---- layer 2 (join stream B's CSR) ----
    cudaStreamWaitEvent(0, c->evCSR, 0);
    gather_kernel<<<gb, 256>>>(c->hh, c->rowptr1, c->csr1);
    dense_kernel<false, true><<<db, 256, dsmem>>>(c->h4, W2, b2, R2, out,
                                                  n_nodes);
}

// round 5
// speedup vs baseline: 1.3992x; 1.0435x over previous
#include <cuda_runtime.h>
#include <cuda_fp16.h>
#include <cstdint>

#define NODES 50000
#define F 64
#define E_MAX 2000000
#define SBS 512
#define SNB ((NODES + SBS - 1) / SBS)   // 98

// ---------------- scratch (device globals; no allocations allowed) ----------
__device__ float4 g_agg4[NODES * (F / 4)];   // [NODES,64] mean-aggregated feats
__device__ float4 g_h4[NODES * (F / 4)];     // [NODES,64] layer-1 output (fp32)
__device__ __half g_xh[NODES * F];           // fp16 copy of x   (gather feed)
__device__ __half g_hh[NODES * F];           // fp16 copy of h   (gather feed)
__device__ int    g_is32;                    // 1 if edge indices are int32

// CSR scratch, sets 0 (layer 1) and 1 (layer 2)
__device__ int g_cnt0[NODES],  g_incl0[NODES], g_bsum0[SNB];
__device__ int g_rowptr0[NODES + 1], g_cursor0[NODES], g_csr0[E_MAX];
__device__ int g_cnt1[NODES],  g_incl1[NODES], g_bsum1[SNB];
__device__ int g_rowptr1[NODES + 1], g_cursor1[NODES], g_csr1[E_MAX];

// ---------------- f32x2 packed-FMA helpers (FFMA2, sm_100+) ------------------
__device__ __forceinline__ unsigned long long pk2(float a) {
    unsigned long long r;
    asm("mov.b64 %0, {%1, %1};" : "=l"(r) : "f"(a));
    return r;
}
__device__ __forceinline__ void fma2(unsigned long long& d,
                                     unsigned long long a,
                                     unsigned long long b) {
    asm("fma.rn.f32x2 %0, %1, %2, %0;" : "+l"(d) : "l"(a), "l"(b));
}
__device__ __forceinline__ float2 up2(unsigned long long v) {
    float2 f;
    asm("mov.b64 {%0, %1}, %2;" : "=f"(f.x), "=f"(f.y) : "l"(v));
    return f;
}

// ---------------- prep: sniff dtype + zero counts + x->fp16 ------------------
// Block 0 additionally runs the dtype sniff (no other block depends on it
// within this kernel; count_both launches after and sees the result).
__global__ void prep_kernel(const long long* __restrict__ e0,
                            const float* __restrict__ x) {
    int i = blockIdx.x * blockDim.x + threadIdx.x;
    if (blockIdx.x == 0) {
        long long v = e0[threadIdx.x];
        int bad = (v < 0 || v >= (long long)NODES) ? 1 : 0;
        bad = __syncthreads_or(bad);
        if (threadIdx.x == 0) g_is32 = bad;
    }
    if (i < NODES) { g_cnt0[i] = 0; g_cnt1[i] = 0; }
    if (i < NODES * (F / 4)) {
        float4 v = ((const float4*)x)[i];
        union { __half2 h[2]; uint2 u; } cv;
        cv.h[0] = __floats2half2_rn(v.x, v.y);
        cv.h[1] = __floats2half2_rn(v.z, v.w);
        ((uint2*)g_xh)[i] = cv.u;
    }
}

// ---------------- count both layers: 4 edges x 2 lists per thread -----------
__global__ void count_both_kernel(const void* __restrict__ e0,
                                  const void* __restrict__ e1, int E) {
    int base = (blockIdx.x * blockDim.x + threadIdx.x) * 4;
    if (base >= E) return;
    int m = min(4, E - base);
    int c0[4], c1[4];
    if (g_is32) {
        const int* p0 = (const int*)e0 + E + base;
        const int* p1 = (const int*)e1 + E + base;
#pragma unroll
        for (int k = 0; k < 4; k++) {
            c0[k] = (k < m) ? __ldg(p0 + k) : 0;
            c1[k] = (k < m) ? __ldg(p1 + k) : 0;
        }
    } else {
        const long long* p0 = (const long long*)e0 + E + base;
        const long long* p1 = (const long long*)e1 + E + base;
#pragma unroll
        for (int k = 0; k < 4; k++) {
            c0[k] = (k < m) ? (int)__ldg(p0 + k) : 0;
            c1[k] = (k < m) ? (int)__ldg(p1 + k) : 0;
        }
    }
#pragma unroll
    for (int k = 0; k < 4; k++)
        if (k < m) {
            atomicAdd(&g_cnt0[c0[k]], 1);   // compiles to RED (result unused)
            atomicAdd(&g_cnt1[c1[k]], 1);
        }
}

// ---------------- scans (grid.y selects layer set) ---------------------------
__global__ void __launch_bounds__(SBS) scan1_kernel() {
    const int* cnt = blockIdx.y ? g_cnt1 : g_cnt0;
    int* incl = blockIdx.y ? g_incl1 : g_incl0;
    int* bsum = blockIdx.y ? g_bsum1 : g_bsum0;
    int tid = threadIdx.x;
    int i = blockIdx.x * SBS + tid;
    int v = (i < NODES) ? cnt[i] : 0;
    int lane = tid & 31, warp = tid >> 5;
    int x = v;
#pragma unroll
    for (int o = 1; o < 32; o <<= 1) {
        int y = __shfl_up_sync(0xFFFFFFFFu, x, o);
        if (lane >= o) x += y;
    }
    __shared__ int ws[SBS / 32];
    if (lane == 31) ws[warp] = x;
    __syncthreads();
    if (warp == 0) {
        int s = (lane < SBS / 32) ? ws[lane] : 0;
#pragma unroll
        for (int o = 1; o < 32; o <<= 1) {
            int y = __shfl_up_sync(0xFFFFFFFFu, s, o);
            if (lane >= o) s += y;
        }
        if (lane < SBS / 32) ws[lane] = s;
    }
    __syncthreads();
    if (warp > 0) x += ws[warp - 1];
    if (i < NODES) incl[i] = x;
    if (tid == SBS - 1) bsum[blockIdx.x] = x;
}

__global__ void scan2_kernel() {        // grid = 2, 128 threads each
    int* bsum = blockIdx.x ? g_bsum1 : g_bsum0;
    int tid = threadIdx.x;
    int v = (tid < SNB) ? bsum[tid] : 0;
    int lane = tid & 31, warp = tid >> 5;
    int x = v;
#pragma unroll
    for (int o = 1; o < 32; o <<= 1) {
        int y = __shfl_up_sync(0xFFFFFFFFu, x, o);
        if (lane >= o) x += y;
    }
    __shared__ int ws[4];
    if (lane == 31) ws[warp] = x;
    __syncthreads();
    int off = 0;
    for (int w = 0; w < warp; w++) off += ws[w];
    x += off;
    if (tid < SNB) bsum[tid] = x - v;   // exclusive
}

__global__ void scan3_kernel() {
    int i = blockIdx.x * blockDim.x + threadIdx.x;
    if (i >= NODES) return;
    if (blockIdx.y == 0) {
        int val = g_incl0[i] + g_bsum0[i / SBS];
        g_rowptr0[i + 1] = val;
        g_cursor0[i] = val - g_cnt0[i];
        if (i == 0) g_rowptr0[0] = 0;
    } else {
        int val = g_incl1[i] + g_bsum1[i / SBS];
        g_rowptr1[i + 1] = val;
        g_cursor1[i] = val - g_cnt1[i];
        if (i == 0) g_rowptr1[0] = 0;
    }
}

// ---------------- place both layers: 4 edges x 2 lists per thread -----------
__global__ void place_both_kernel(const void* __restrict__ e0,
                                  const void* __restrict__ e1, int E) {
    int base = (blockIdx.x * blockDim.x + threadIdx.x) * 4;
    if (base >= E) return;
    int m = min(4, E - base);
    int r0[4], c0[4], r1[4], c1[4];
    if (g_is32) {
        const int* p0 = (const int*)e0;
        const int* p1 = (const int*)e1;
#pragma unroll
        for (int k = 0; k < 4; k++) {
            r0[k] = (k < m) ? __ldg(p0 + base + k) : 0;
            c0[k] = (k < m) ? __ldg(p0 + E + base + k) : 0;
            r1[k] = (k < m) ? __ldg(p1 + base + k) : 0;
            c1[k] = (k < m) ? __ldg(p1 + E + base + k) : 0;
        }
    } else {
        const long long* p0 = (const long long*)e0;
        const long long* p1 = (const long long*)e1;
#pragma unroll
        for (int k = 0; k < 4; k++) {
            r0[k] = (k < m) ? (int)__ldg(p0 + base + k) : 0;
            c0[k] = (k < m) ? (int)__ldg(p0 + E + base + k) : 0;
            r1[k] = (k < m) ? (int)__ldg(p1 + base + k) : 0;
            c1[k] = (k < m) ? (int)__ldg(p1 + E + base + k) : 0;
        }
    }
#pragma unroll
    for (int k = 0; k < 4; k++)
        if (k < m) {
            g_csr0[atomicAdd(&g_cursor0[c0[k]], 1)] = r0[k];
            g_csr1[atomicAdd(&g_cursor1[c1[k]], 1)] = r1[k];
        }
}

// ---------------- gather-side mean aggregation (fp16 feed, fp32 acc) --------
// one warp per node; each lane owns 2 columns (half2); unroll 8 for MLP
template <int SET>
__global__ void __launch_bounds__(256) gather_kernel(
    const __half* __restrict__ srch) {
    const int* rowptr = SET ? g_rowptr1 : g_rowptr0;
    const int* csr = SET ? g_csr1 : g_csr0;
    int tid = threadIdx.x;
    int node = blockIdx.x * 8 + (tid >> 5);
    if (node >= NODES) return;
    int lane = tid & 31;
    int s = __ldg(&rowptr[node]);
    int e = __ldg(&rowptr[node + 1]);
    float ax = 0.f, ay = 0.f;
    int i = s;
    for (; i + 8 <= e; i += 8) {
        int r[8];
#pragma unroll
        for (int k = 0; k < 8; k++) r[k] = __ldg(&csr[i + k]);
        float2 v[8];
#pragma unroll
        for (int k = 0; k < 8; k++)
            v[k] = __half22float2(*((const __half2*)(srch + (size_t)r[k] * F) + lane));
#pragma unroll
        for (int k = 0; k < 8; k++) { ax += v[k].x; ay += v[k].y; }
    }
    for (; i < e; i++) {
        int r = __ldg(&csr[i]);
        float2 v = __half22float2(*((const __half2*)(srch + (size_t)r * F) + lane));
        ax += v.x; ay += v.y;
    }
    float inv = 1.f / (float)max(e - s, 1);
    float2 o; o.x = ax * inv; o.y = ay * inv;
    *(float2*)((float*)g_agg4 + (size_t)node * F + lane * 2) = o;
}

// ---------------- fused dense: out = agg@W + b + xin@R ----------------------
// 128 nodes x 64 outputs, 256 threads, 8x4 blocking via packed FFMA2.
// RELU path additionally emits fp16 copy of the output into g_hh.
template <bool RELU, bool NORM>
__global__ void __launch_bounds__(256) dense_kernel(
    const float* __restrict__ xin,
    const float* __restrict__ W, const float* __restrict__ bias,
    const float* __restrict__ R, float* __restrict__ out, int n_nodes) {
    extern __shared__ float smem[];
    float* As = smem;                    // [64][132]
    float* Ws = smem + F * 132;          // [64][64]
    float* sb = Ws + F * F;              // [64]

    const float* agg = (const float*)g_agg4;
    int tid = threadIdx.x;
    int n0 = blockIdx.x * 128;

    if (tid < F) sb[tid] = bias[tid];

    unsigned long long acc2[8][2];
#pragma unroll
    for (int a = 0; a < 8; a++) { acc2[a][0] = 0ull; acc2[a][1] = 0ull; }

    int j0 = (tid & 15) * 4;
    int i0 = (tid >> 4) * 8;

#pragma unroll
    for (int c = 0; c < 2; ++c) {
        const float* src = c ? xin : agg;
        const float* wsrc = c ? R : W;
        __syncthreads();
#pragma unroll
        for (int t = 0; t < 8; ++t) {
            int q = tid + 256 * t;          // [0,2048)
            int i = q >> 4;                 // node within tile (0..127)
            int kk = (q & 15) << 2;         // k offset
            int n = n0 + i;
            float4 v = make_float4(0.f, 0.f, 0.f, 0.f);
            if (n < n_nodes) v = *(const float4*)(src + (size_t)n * F + kk);
            As[(kk + 0) * 132 + i] = v.x;
            As[(kk + 1) * 132 + i] = v.y;
            As[(kk + 2) * 132 + i] = v.z;
            As[(kk + 3) * 132 + i] = v.w;
        }
#pragma unroll
        for (int t = 0; t < 4; ++t) {
            int q = tid + 256 * t;          // [0,1024)
            *(float4*)(Ws + q * 4) = *(const float4*)(wsrc + q * 4);
        }
        __syncthreads();
#pragma unroll
        for (int k = 0; k < F; ++k) {
            float4 a0 = *(const float4*)&As[k * 132 + i0];
            float4 a1 = *(const float4*)&As[k * 132 + i0 + 4];
            ulonglong2 wv = *(const ulonglong2*)&Ws[k * F + j0];
            unsigned long long p;
            p = pk2(a0.x); fma2(acc2[0][0], p, wv.x); fma2(acc2[0][1], p, wv.y);
            p = pk2(a0.y); fma2(acc2[1][0], p, wv.x); fma2(acc2[1][1], p, wv.y);
            p = pk2(a0.z); fma2(acc2[2][0], p, wv.x); fma2(acc2[2][1], p, wv.y);
            p = pk2(a0.w); fma2(acc2[3][0], p, wv.x); fma2(acc2[3][1], p, wv.y);
            p = pk2(a1.x); fma2(acc2[4][0], p, wv.x); fma2(acc2[4][1], p, wv.y);
            p = pk2(a1.y); fma2(acc2[5][0], p, wv.x); fma2(acc2[5][1], p, wv.y);
            p = pk2(a1.z); fma2(acc2[6][0], p, wv.x); fma2(acc2[6][1], p, wv.y);
            p = pk2(a1.w); fma2(acc2[7][0], p, wv.x); fma2(acc2[7][1], p, wv.y);
        }
    }

    // epilogue
    float o[8][4];
#pragma unroll
    for (int ii = 0; ii < 8; ++ii) {
        float2 lo = up2(acc2[ii][0]);
        float2 hi = up2(acc2[ii][1]);
        o[ii][0] = lo.x + sb[j0 + 0];
        o[ii][1] = lo.y + sb[j0 + 1];
        o[ii][2] = hi.x + sb[j0 + 2];
        o[ii][3] = hi.y + sb[j0 + 3];
        if (RELU) {
            o[ii][0] = fmaxf(o[ii][0], 0.f); o[ii][1] = fmaxf(o[ii][1], 0.f);
            o[ii][2] = fmaxf(o[ii][2], 0.f); o[ii][3] = fmaxf(o[ii][3], 0.f);
        }
    }
    if (NORM) {
        // each row's 64 cols live in 16 lanes of one half-warp -> xor 1,2,4,8
#pragma unroll
        for (int ii = 0; ii < 8; ++ii) {
            float ss = o[ii][0] * o[ii][0] + o[ii][1] * o[ii][1] +
                       o[ii][2] * o[ii][2] + o[ii][3] * o[ii][3];
#pragma unroll
            for (int m = 1; m < 16; m <<= 1)
                ss += __shfl_xor_sync(0xFFFFFFFFu, ss, m);
            float inv = 1.f / fmaxf(sqrtf(ss), 1e-12f);
            o[ii][0] *= inv; o[ii][1] *= inv;
            o[ii][2] *= inv; o[ii][3] *= inv;
        }
    }
#pragma unroll
    for (int ii = 0; ii < 8; ++ii) {
        int n = n0 + i0 + ii;
        if (n < n_nodes) {
            float4 v = make_float4(o[ii][0], o[ii][1], o[ii][2], o[ii][3]);
            *(float4*)(out + (size_t)n * F + j0) = v;
            if (RELU) {   // fp16 copy for the next gather
                union { __half2 h[2]; uint2 u; } cv;
                cv.h[0] = __floats2half2_rn(o[ii][0], o[ii][1]);
                cv.h[1] = __floats2half2_rn(o[ii][2], o[ii][3]);
                *(uint2*)(g_hh + (size_t)n * F + j0) = cv.u;
            }
        }
    }
}

// ---------------- launch -----------------------------------------------------
extern "C" void kernel_launch(void* const* d_in, const int* in_sizes, int n_in,
                              void* d_out, int out_size) {
    const float* x  = (const float*)d_in[0];
    const void*  e0 = d_in[1];
    const void*  e1 = d_in[2];
    const float* W1 = (const float*)d_in[3];
    const float* b1 = (const float*)d_in[4];
    const float* R1 = (const float*)d_in[5];
    const float* W2 = (const float*)d_in[6];
    const float* b2 = (const float*)d_in[7];
    const float* R2 = (const float*)d_in[8];
    float* out = (float*)d_out;

    static float* h4 = nullptr;
    static __half* xh = nullptr;
    static __half* hh = nullptr;
    if (!h4) {
        void* p;
        cudaGetSymbolAddress(&p, g_h4); h4 = (float*)p;
        cudaGetSymbolAddress(&p, g_xh); xh = (__half*)p;
        cudaGetSymbolAddress(&p, g_hh); hh = (__half*)p;
        cudaFuncSetAttribute(dense_kernel<true, false>,
                             cudaFuncAttributeMaxDynamicSharedMemorySize, 51200);
        cudaFuncSetAttribute(dense_kernel<false, true>,
                             cudaFuncAttributeMaxDynamicSharedMemorySize, 51200);
    }

    int E = in_sizes[1] / 2;
    int n_nodes = out_size / F;              // 50000
    int dsmem = (F * 132 + F * F + F) * 4;   // 50432 B

    int eb4 = (E / 4 + 255) / 256;
    int nb = (NODES + 255) / 256;
    int pb = (NODES * F / 4 + 255) / 256;    // prep covers conversion range
    int gb = (NODES + 7) / 8;
    int db = (n_nodes + 127) / 128;

    prep_kernel<<<pb, 256>>>((const long long*)e0, x);
    count_both_kernel<<<eb4, 256>>>(e0, e1, E);
    scan1_kernel<<<dim3(SNB, 2), SBS>>>();
    scan2_kernel<<<2, 128>>>();
    scan3_kernel<<<dim3(nb, 2), 256>>>();
    place_both_kernel<<<eb4, 256>>>(e0, e1, E);

    // layer 1
    gather_kernel<0><<<gb, 256>>>(xh);
    dense_kernel<true, false><<<db, 256, dsmem>>>(x, W1, b1, R1, h4, n_nodes);

    // layer 2
    gather_kernel<1><<<gb, 256>>>(hh);
    dense_kernel<false, true><<<db, 256, dsmem>>>(h4, W2, b2, R2, out, n_nodes);
}